// round 5
// baseline (speedup 1.0000x reference)
#include <cuda_runtime.h>
#include <cstdint>

// ============================================================================
// LinearCapsPro:  out[b,c] = sqrt( u_c^T (W_c W_c^T + eps I)^{-1} u_c ),
//                 u_c = W_c x_b
// Restructured:   G_c = R_c R_c^T (Cholesky)  =>  out[b,c] = || (R_c^{-1} W_c) x_b ||
// Prep W' = R^{-1} W (tiny), then ONE tf32 GEMM y = x @ W'^T with a fused
// sum-of-squares + sqrt epilogue (y never touches memory).
//
// NOTE: this environment emits compute_100 PTX (no "a" features) -> tcgen05
// unavailable. Use mma.sync.m16n8k8.tf32 + cp.async (Ampere-class path).
// ============================================================================

#define BATCH 8192
#define KDIM 512
#define NTOT 8192          // C*D
#define NUM_CAPS 1024
#define EPS_REG 1e-4f

#define BM 128
#define BN 256
#define BK 32              // 32 fp32 = 128B rows
#define STAGES 4
#define KITERS (KDIM / BK) // 16

#define A_BYTES (BM * BK * 4)           // 16384
#define B_BYTES (BN * BK * 4)           // 32768
#define STAGE_BYTES (A_BYTES + B_BYTES) // 49152
#define SMEM_TOTAL (STAGES * STAGE_BYTES) // 196608

// Scratch (static device globals: allocation-free per harness rules).
// Stored in "fragment-order" permuted k layout (see permk).
__device__ __align__(256) float g_xr[BATCH * KDIM];
__device__ __align__(256) float g_wp[NTOT * KDIM];

// ---------------------------------------------------------------------------
// cvt to tf32 requires a .b32 destination register (PTX ISA) -> "=r".
__device__ __forceinline__ float to_tf32(float a) {
    uint32_t r;
    asm("cvt.rna.tf32.f32 %0, %1;" : "=r"(r) : "f"(a));
    return __uint_as_float(r);
}

// Column permutation within each 32-float k-block so that an m16n8k8 tf32
// fragment's 4 values per (thread,row) are 16B-contiguous:
//   p = (k%4)*8 + (k%32)/4   (within block), blocks stay in place.
__device__ __forceinline__ int permk(int k) {
    return (k & ~31) | ((k & 3) << 3) | ((k & 31) >> 2);
}

__device__ __forceinline__ uint32_t smem_u32(const void* p) {
    uint32_t a;
    asm("{ .reg .u64 t; cvta.to.shared.u64 t, %1; cvt.u32.u64 %0, t; }"
        : "=r"(a) : "l"(p));
    return a;
}

__device__ __forceinline__ void cp_async16(uint32_t dst, const void* src) {
    asm volatile("cp.async.cg.shared.global [%0], [%1], 16;"
                 :: "r"(dst), "l"(src) : "memory");
}
__device__ __forceinline__ void cp_commit() {
    asm volatile("cp.async.commit_group;" ::: "memory");
}
__device__ __forceinline__ void cp_wait2() {
    asm volatile("cp.async.wait_group 2;" ::: "memory");
}

__device__ __forceinline__ void lds128(float4& v, uint32_t addr) {
    asm volatile("ld.shared.v4.f32 {%0,%1,%2,%3}, [%4];"
                 : "=f"(v.x), "=f"(v.y), "=f"(v.z), "=f"(v.w)
                 : "r"(addr));
}

__device__ __forceinline__ void mma_tf32(float* c,
                                         float a0, float a1, float a2, float a3,
                                         float b0, float b1) {
    asm volatile(
        "mma.sync.aligned.m16n8k8.row.col.f32.tf32.tf32.f32 "
        "{%0,%1,%2,%3}, {%4,%5,%6,%7}, {%8,%9}, {%0,%1,%2,%3};"
        : "+f"(c[0]), "+f"(c[1]), "+f"(c[2]), "+f"(c[3])
        : "r"(__float_as_uint(a0)), "r"(__float_as_uint(a1)),
          "r"(__float_as_uint(a2)), "r"(__float_as_uint(a3)),
          "r"(__float_as_uint(b0)), "r"(__float_as_uint(b1)));
}

// ---------------------------------------------------------------------------
// Setup 1: round x to nearest tf32, store in permuted layout.
// ---------------------------------------------------------------------------
__global__ void round_x_kernel(const float* __restrict__ x) {
    int i = blockIdx.x * 256 + threadIdx.x;   // grid covers BATCH*KDIM exactly
    float v = x[i];
    int row = i >> 9;
    int k = i & 511;
    g_xr[(row << 9) | permk(k)] = to_tf32(v);
}

// ---------------------------------------------------------------------------
// Setup 2: per capsule c — G = W_c W_c^T + eps I, Cholesky G = R R^T,
// W'_c = R^{-1} W_c, rounded to tf32, permuted layout. One block per capsule.
// ---------------------------------------------------------------------------
__global__ __launch_bounds__(256) void prep_w_kernel(const float* __restrict__ w) {
    __shared__ float sW[8][516];
    __shared__ float sG[8][8];
    __shared__ float sR[8][8];
    __shared__ float sRinv[8];
    int c = blockIdx.x;
    int tid = threadIdx.x;

    for (int i = tid; i < 8 * 512; i += 256)
        sW[i >> 9][i & 511] = w[c * 4096 + i];
    __syncthreads();

    if (tid < 64) {
        int d = tid >> 3, e = tid & 7;
        float s = 0.f;
        #pragma unroll 8
        for (int k = 0; k < 512; k++) s += sW[d][k] * sW[e][k];
        sG[d][e] = s + (d == e ? EPS_REG : 0.f);
    }
    __syncthreads();

    if (tid == 0) {
        float R[8][8];
        #pragma unroll
        for (int i = 0; i < 8; i++) {
            #pragma unroll
            for (int j = 0; j <= i; j++) {
                float s = sG[i][j];
                for (int k = 0; k < j; k++) s -= R[i][k] * R[j][k];
                if (i == j) R[i][i] = sqrtf(s);
                else        R[i][j] = s / R[j][j];
            }
        }
        #pragma unroll
        for (int i = 0; i < 8; i++) {
            sRinv[i] = 1.0f / R[i][i];
            #pragma unroll
            for (int j = 0; j <= i; j++) sR[i][j] = R[i][j];
        }
    }
    __syncthreads();

    for (int k = tid; k < 512; k += 256) {
        float y[8];
        #pragma unroll
        for (int d = 0; d < 8; d++) {
            float t = sW[d][k];
            #pragma unroll
            for (int j = 0; j < 8; j++)
                if (j < d) t -= sR[d][j] * y[j];
            y[d] = t * sRinv[d];
        }
        #pragma unroll
        for (int d = 0; d < 8; d++)
            g_wp[(size_t)(c * 8 + d) * KDIM + permk(k)] = to_tf32(y[d]);
    }
}

// ---------------------------------------------------------------------------
// Main GEMM: 128x256 tile per CTA, 256 threads (8 warps, 2m x 4n, 64x64 warp
// tiles). 4-stage cp.async pipeline. SMEM rows = 32 floats = 8 x 16B chunks,
// chunk c stored at c ^ (row&7) (conflict-free LDS.128 fragment loads).
// Fused epilogue: out[b,cap] = sqrt(sum_{d<8} y^2) via quad butterfly.
// ---------------------------------------------------------------------------
__global__ __launch_bounds__(256, 1) void caps_gemm_kernel(float* __restrict__ out) {
    extern __shared__ char smem[];
    const uint32_t sbase = smem_u32(smem);
    const int tid = threadIdx.x;
    const int lane = tid & 31;
    const int wid = tid >> 5;
    const int warp_m = wid & 1;       // 2 warps along M
    const int warp_n = wid >> 1;      // 4 warps along N
    const int g = lane >> 2;          // groupID
    const int tg = lane & 3;          // threadID_in_group
    const int m0 = blockIdx.y * BM;
    const int n0 = blockIdx.x * BN;

    // Producer mapping: 12 x 16B chunks per thread per stage.
    // i in [0,4): A tile (128 rows x 8 chunks); i in [4,12): B tile (256 x 8).
    auto issue = [&](int kk, int s) {
        uint32_t st = sbase + s * STAGE_BYTES;
        const char* xa = (const char*)g_xr + (size_t)kk * 128;
        const char* wa = (const char*)g_wp + (size_t)kk * 128;
        #pragma unroll
        for (int i = 0; i < 4; i++) {
            int ch = i * 256 + tid;           // 0..1023
            int row = ch >> 3, c = ch & 7;
            cp_async16(st + (uint32_t)(row * 128 + ((c ^ (row & 7)) << 4)),
                       xa + (size_t)(m0 + row) * 2048 + c * 16);
        }
        #pragma unroll
        for (int i = 0; i < 8; i++) {
            int ch = i * 256 + tid;           // 0..2047
            int row = ch >> 3, c = ch & 7;
            cp_async16(st + (uint32_t)(A_BYTES + row * 128 + ((c ^ (row & 7)) << 4)),
                       wa + (size_t)(n0 + row) * 2048 + c * 16);
        }
        cp_commit();
    };

    // Prologue: fill first 3 stages.
    #pragma unroll
    for (int s = 0; s < STAGES - 1; s++) issue(s, s);

    float acc[4][8][4];
    #pragma unroll
    for (int mf = 0; mf < 4; mf++)
        #pragma unroll
        for (int nf = 0; nf < 8; nf++)
            #pragma unroll
            for (int r = 0; r < 4; r++) acc[mf][nf][r] = 0.f;

    // Consumer base offsets (bytes from stage base). All needed rows have
    // (row & 7) == g, so the phys chunk is ((2*tg+h)^g) uniformly.
    uint32_t aRow[4], bRow[8];
    #pragma unroll
    for (int mf = 0; mf < 4; mf++) aRow[mf] = (warp_m * 64 + mf * 16 + g) * 128;
    #pragma unroll
    for (int nf = 0; nf < 8; nf++) bRow[nf] = A_BYTES + (warp_n * 64 + nf * 8 + g) * 128;

    #pragma unroll 1
    for (int kk = 0; kk < KITERS; kk++) {
        cp_wait2();
        __syncthreads();
        if (kk + STAGES - 1 < KITERS) {
            issue(kk + STAGES - 1, (kk + STAGES - 1) & (STAGES - 1));
        } else {
            cp_commit();   // empty group keeps wait_group accounting exact (tail fix)
        }

        uint32_t st = sbase + (uint32_t)(kk & (STAGES - 1)) * STAGE_BYTES;
        #pragma unroll
        for (int h = 0; h < 2; h++) {
            uint32_t ck = (uint32_t)(((2 * tg + h) ^ g) << 4);
            float4 aLo[4], aHi[4];
            #pragma unroll
            for (int mf = 0; mf < 4; mf++) {
                lds128(aLo[mf], st + aRow[mf] + ck);
                lds128(aHi[mf], st + aRow[mf] + 1024 + ck);  // +8 rows
            }
            #pragma unroll
            for (int nfg = 0; nfg < 2; nfg++) {
                float4 bF[4];
                #pragma unroll
                for (int q = 0; q < 4; q++)
                    lds128(bF[q], st + bRow[nfg * 4 + q] + ck);
                // kstep j=0 within half: words .x/.y ; j=1: .z/.w
                #pragma unroll
                for (int mf = 0; mf < 4; mf++) {
                    #pragma unroll
                    for (int q = 0; q < 4; q++) {
                        mma_tf32(acc[mf][nfg * 4 + q],
                                 aLo[mf].x, aHi[mf].x, aLo[mf].y, aHi[mf].y,
                                 bF[q].x, bF[q].y);
                    }
                }
                #pragma unroll
                for (int mf = 0; mf < 4; mf++) {
                    #pragma unroll
                    for (int q = 0; q < 4; q++) {
                        mma_tf32(acc[mf][nfg * 4 + q],
                                 aLo[mf].z, aHi[mf].z, aLo[mf].w, aHi[mf].w,
                                 bF[q].z, bF[q].w);
                    }
                }
            }
        }
    }

    // ------------------- fused epilogue ------------------------------------
    // Each m16n8 accumulator frag covers exactly one capsule (8 n-cols).
    // Thread holds cols (2tg, 2tg+1) for rows g and g+8 -> quad butterfly
    // over tg gives the full 8-col sum of squares.
    #pragma unroll
    for (int mf = 0; mf < 4; mf++) {
        #pragma unroll
        for (int nf = 0; nf < 8; nf++) {
            float* c = acc[mf][nf];
            float s0 = c[0] * c[0] + c[1] * c[1];
            float s1 = c[2] * c[2] + c[3] * c[3];
            s0 += __shfl_xor_sync(0xffffffffu, s0, 1);
            s0 += __shfl_xor_sync(0xffffffffu, s0, 2);
            s1 += __shfl_xor_sync(0xffffffffu, s1, 1);
            s1 += __shfl_xor_sync(0xffffffffu, s1, 2);
            if (tg == 0) {
                int row = m0 + warp_m * 64 + mf * 16 + g;
                int cap = (n0 + warp_n * 64 + nf * 8) >> 3;
                out[row * NUM_CAPS + cap] = sqrtf(s0);
                out[(row + 8) * NUM_CAPS + cap] = sqrtf(s1);
            }
        }
    }
}

// ---------------------------------------------------------------------------
extern "C" void kernel_launch(void* const* d_in, const int* in_sizes, int n_in,
                              void* d_out, int out_size) {
    (void)in_sizes; (void)n_in; (void)out_size;
    const float* x = (const float*)d_in[0];
    // d_in[1] = eye (unused; eps*I applied analytically)
    const float* w = (const float*)d_in[2];
    float* out = (float*)d_out;

    round_x_kernel<<<(BATCH * KDIM) / 256, 256>>>(x);
    prep_w_kernel<<<NUM_CAPS, 256>>>(w);

    cudaFuncSetAttribute(caps_gemm_kernel,
                         cudaFuncAttributeMaxDynamicSharedMemorySize, SMEM_TOTAL);
    caps_gemm_kernel<<<dim3(NTOT / BN, BATCH / BM), 256, SMEM_TOTAL>>>(out);
}

// round 6
// speedup vs baseline: 1.7939x; 1.7939x over previous
#include <cuda_runtime.h>
#include <cuda_fp16.h>
#include <cstdint>

// ============================================================================
// LinearCapsPro:  out[b,c] = sqrt( u_c^T (W_c W_c^T + eps I)^{-1} u_c ),
//                 u_c = W_c x_b
// Restructured:   G_c = R_c R_c^T (Cholesky)  =>  out[b,c] = || (R_c^{-1} W_c) x_b ||
// Prep W' = R^{-1} W (tiny), then ONE fp16 GEMM y = x @ W'^T with a fused
// sum-of-squares + sqrt epilogue (y never touches memory).
//
// R5 evidence: tf32 m16n8k8 version ran at the legacy-mma issue ceiling
// (~146 TF/s). fp16 m16n8k16 = 2x K per instruction, same 10-bit mantissa as
// tf32 with fp32 accumulation -> ~2x GEMM throughput at equal precision.
// ============================================================================

#define BATCH 8192
#define KDIM 512
#define NTOT 8192          // C*D
#define NUM_CAPS 1024
#define EPS_REG 1e-4f

#define BM 128
#define BN 256
#define BK 64              // 64 fp16 = 128B rows
#define STAGES 4
#define KITERS (KDIM / BK) // 8

#define A_BYTES (BM * BK * 2)           // 16384
#define B_BYTES (BN * BK * 2)           // 32768
#define STAGE_BYTES (A_BYTES + B_BYTES) // 49152
#define SMEM_TOTAL (STAGES * STAGE_BYTES) // 196608

// Scratch (static device globals: allocation-free per harness rules).
// fp16, "fragment-order" permuted k layout within each 32-k block:
//   k = 32*blk + 16h + 8u + 2t + e  ->  p = 32*blk + 8t + 4h + 2u + e
// so thread tg's m16n8k16 fragments (both h-steps) are one 16B chunk at t*16.
__device__ __align__(256) __half g_xh[BATCH * KDIM];
__device__ __align__(256) __half g_wph[NTOT * KDIM];

// ---------------------------------------------------------------------------
__device__ __forceinline__ int permh(int k) {
    return (k & ~31) | (((k >> 1) & 3) << 3) | (((k >> 4) & 1) << 2)
         | (((k >> 3) & 1) << 1) | (k & 1);
}

__device__ __forceinline__ uint32_t smem_u32(const void* p) {
    uint32_t a;
    asm("{ .reg .u64 t; cvta.to.shared.u64 t, %1; cvt.u32.u64 %0, t; }"
        : "=r"(a) : "l"(p));
    return a;
}

__device__ __forceinline__ void cp_async16(uint32_t dst, const void* src) {
    asm volatile("cp.async.cg.shared.global [%0], [%1], 16;"
                 :: "r"(dst), "l"(src) : "memory");
}
__device__ __forceinline__ void cp_commit() {
    asm volatile("cp.async.commit_group;" ::: "memory");
}
__device__ __forceinline__ void cp_wait2() {
    asm volatile("cp.async.wait_group 2;" ::: "memory");
}

__device__ __forceinline__ void lds128u(uint4& v, uint32_t addr) {
    asm volatile("ld.shared.v4.u32 {%0,%1,%2,%3}, [%4];"
                 : "=r"(v.x), "=r"(v.y), "=r"(v.z), "=r"(v.w)
                 : "r"(addr));
}

// m16n8k16 fp16 MMA, fp32 accumulate.
__device__ __forceinline__ void mma_f16(float* c,
                                        uint32_t a0, uint32_t a1,
                                        uint32_t a2, uint32_t a3,
                                        uint32_t b0, uint32_t b1) {
    asm volatile(
        "mma.sync.aligned.m16n8k16.row.col.f32.f16.f16.f32 "
        "{%0,%1,%2,%3}, {%4,%5,%6,%7}, {%8,%9}, {%0,%1,%2,%3};"
        : "+f"(c[0]), "+f"(c[1]), "+f"(c[2]), "+f"(c[3])
        : "r"(a0), "r"(a1), "r"(a2), "r"(a3), "r"(b0), "r"(b1));
}

// ---------------------------------------------------------------------------
// Setup 1: convert x to fp16, permuted layout. Thread reads one float4
// (coalesced); the two half2 pairs land at permuted word positions.
// ---------------------------------------------------------------------------
__global__ void conv_x_kernel(const float4* __restrict__ x4) {
    int i = blockIdx.x * 256 + threadIdx.x;   // covers BATCH*KDIM/4 exactly
    float4 v = x4[i];
    int row = i >> 7;            // 128 float4 per row
    int k = (i & 127) << 2;
    __half2* dst = reinterpret_cast<__half2*>(g_xh + (size_t)row * KDIM);
    dst[permh(k) >> 1]     = __floats2half2_rn(v.x, v.y);
    dst[permh(k + 2) >> 1] = __floats2half2_rn(v.z, v.w);
}

// ---------------------------------------------------------------------------
// Setup 2: per capsule c — G = W_c W_c^T + eps I (fp32), Cholesky G = R R^T,
// W'_c = R^{-1} W_c, stored fp16 permuted. One block per capsule.
// ---------------------------------------------------------------------------
__global__ __launch_bounds__(256) void prep_w_kernel(const float* __restrict__ w) {
    __shared__ float sW[8][516];
    __shared__ float sG[8][8];
    __shared__ float sR[8][8];
    __shared__ float sRinv[8];
    int c = blockIdx.x;
    int tid = threadIdx.x;

    for (int i = tid; i < 8 * 512; i += 256)
        sW[i >> 9][i & 511] = w[c * 4096 + i];
    __syncthreads();

    if (tid < 64) {
        int d = tid >> 3, e = tid & 7;
        float s = 0.f;
        #pragma unroll 8
        for (int k = 0; k < 512; k++) s += sW[d][k] * sW[e][k];
        sG[d][e] = s + (d == e ? EPS_REG : 0.f);
    }
    __syncthreads();

    if (tid == 0) {
        float R[8][8];
        #pragma unroll
        for (int i = 0; i < 8; i++) {
            #pragma unroll
            for (int j = 0; j <= i; j++) {
                float s = sG[i][j];
                for (int k = 0; k < j; k++) s -= R[i][k] * R[j][k];
                if (i == j) R[i][i] = sqrtf(s);
                else        R[i][j] = s / R[j][j];
            }
        }
        #pragma unroll
        for (int i = 0; i < 8; i++) {
            sRinv[i] = 1.0f / R[i][i];
            #pragma unroll
            for (int j = 0; j <= i; j++) sR[i][j] = R[i][j];
        }
    }
    __syncthreads();

    for (int k = tid; k < 512; k += 256) {
        float y[8];
        #pragma unroll
        for (int d = 0; d < 8; d++) {
            float t = sW[d][k];
            #pragma unroll
            for (int j = 0; j < 8; j++)
                if (j < d) t -= sR[d][j] * y[j];
            y[d] = t * sRinv[d];
        }
        int pk = permh(k);
        #pragma unroll
        for (int d = 0; d < 8; d++)
            g_wph[(size_t)(c * 8 + d) * KDIM + pk] = __float2half_rn(y[d]);
    }
}

// ---------------------------------------------------------------------------
// Main GEMM: 128x256 tile per CTA, 256 threads (8 warps, 2m x 4n, 64x64 warp
// tiles). 4-stage cp.async pipeline, BK=64 (128B rows). SMEM chunk swizzle
// c ^ ((row&1)<<2) keeps LDS.128 conflict-free with 128B rows.
// Fused epilogue: out[b,cap] = sqrt(sum_{d<8} y^2), vectorized float4 stores.
// ---------------------------------------------------------------------------
__global__ __launch_bounds__(256, 1) void caps_gemm_kernel(float* __restrict__ out) {
    extern __shared__ char smem[];
    const uint32_t sbase = smem_u32(smem);
    const int tid = threadIdx.x;
    const int lane = tid & 31;
    const int wid = tid >> 5;
    const int warp_m = wid & 1;       // 2 warps along M
    const int warp_n = wid >> 1;      // 4 warps along N
    const int g = lane >> 2;          // groupID
    const int tg = lane & 3;          // threadID_in_group
    const int m0 = blockIdx.y * BM;
    const int n0 = blockIdx.x * BN;

    // Producer mapping: 12 x 16B chunks per thread per stage.
    // A tile: 128 rows x 8 chunks; B tile: 256 rows x 8 chunks.
    auto issue = [&](int kk, int s) {
        uint32_t st = sbase + s * STAGE_BYTES;
        const char* xa = (const char*)g_xh + (size_t)kk * 128;
        const char* wa = (const char*)g_wph + (size_t)kk * 128;
        #pragma unroll
        for (int i = 0; i < 4; i++) {
            int ch = i * 256 + tid;           // 0..1023
            int row = ch >> 3, c = ch & 7;
            cp_async16(st + (uint32_t)(row * 128 + ((c ^ ((row & 1) << 2)) << 4)),
                       xa + (size_t)(m0 + row) * 1024 + c * 16);
        }
        #pragma unroll
        for (int i = 0; i < 8; i++) {
            int ch = i * 256 + tid;           // 0..2047
            int row = ch >> 3, c = ch & 7;
            cp_async16(st + (uint32_t)(A_BYTES + row * 128 + ((c ^ ((row & 1) << 2)) << 4)),
                       wa + (size_t)(n0 + row) * 1024 + c * 16);
        }
        cp_commit();
    };

    // Prologue: fill first 3 stages.
    #pragma unroll
    for (int s = 0; s < STAGES - 1; s++) issue(s, s);

    float acc[4][8][4];
    #pragma unroll
    for (int mf = 0; mf < 4; mf++)
        #pragma unroll
        for (int nf = 0; nf < 8; nf++)
            #pragma unroll
            for (int r = 0; r < 4; r++) acc[mf][nf][r] = 0.f;

    // Consumer base offsets. All rows a thread touches share parity (g&1).
    uint32_t aRow[4], bRow[8];
    #pragma unroll
    for (int mf = 0; mf < 4; mf++) aRow[mf] = (warp_m * 64 + mf * 16 + g) * 128;
    #pragma unroll
    for (int nf = 0; nf < 8; nf++) bRow[nf] = A_BYTES + (warp_n * 64 + nf * 8 + g) * 128;
    const uint32_t par = (uint32_t)((g & 1) << 2);

    #pragma unroll 1
    for (int kk = 0; kk < KITERS; kk++) {
        cp_wait2();
        __syncthreads();
        if (kk + STAGES - 1 < KITERS) {
            issue(kk + STAGES - 1, (kk + STAGES - 1) & (STAGES - 1));
        } else {
            cp_commit();   // empty group keeps wait_group accounting exact
        }

        uint32_t st = sbase + (uint32_t)(kk & (STAGES - 1)) * STAGE_BYTES;
        #pragma unroll
        for (int b = 0; b < 2; b++) {          // two 32-k blocks per stage
            uint32_t ck = (uint32_t)(((4 * b + tg) ^ par) << 4);
            uint4 aLo[4], aHi[4];
            #pragma unroll
            for (int mf = 0; mf < 4; mf++) {
                lds128u(aLo[mf], st + aRow[mf] + ck);
                lds128u(aHi[mf], st + aRow[mf] + 1024 + ck);  // +8 rows
            }
            #pragma unroll
            for (int nfg = 0; nfg < 2; nfg++) {
                uint4 bF[4];
                #pragma unroll
                for (int q = 0; q < 4; q++)
                    lds128u(bF[q], st + bRow[nfg * 4 + q] + ck);
                // h=0: words (x,y); h=1: words (z,w)
                #pragma unroll
                for (int mf = 0; mf < 4; mf++) {
                    #pragma unroll
                    for (int q = 0; q < 4; q++) {
                        mma_f16(acc[mf][nfg * 4 + q],
                                aLo[mf].x, aHi[mf].x, aLo[mf].y, aHi[mf].y,
                                bF[q].x, bF[q].y);
                    }
                }
                #pragma unroll
                for (int mf = 0; mf < 4; mf++) {
                    #pragma unroll
                    for (int q = 0; q < 4; q++) {
                        mma_f16(acc[mf][nfg * 4 + q],
                                aLo[mf].z, aHi[mf].z, aLo[mf].w, aHi[mf].w,
                                bF[q].z, bF[q].w);
                    }
                }
            }
        }
    }

    // ------------------- fused epilogue ------------------------------------
    // Each m16n8 accumulator frag covers exactly one capsule (8 n-cols).
    // Quad butterfly over tg sums the 8-col squares; tg==0 lanes then hold
    // the 8 consecutive capsules of this warp tile -> vectorized stores.
    const int capbase = (n0 >> 3) + warp_n * 8;
    #pragma unroll
    for (int mf = 0; mf < 4; mf++) {
        float r0[8], r1[8];
        #pragma unroll
        for (int nf = 0; nf < 8; nf++) {
            float* c = acc[mf][nf];
            float s0 = c[0] * c[0] + c[1] * c[1];
            float s1 = c[2] * c[2] + c[3] * c[3];
            s0 += __shfl_xor_sync(0xffffffffu, s0, 1);
            s0 += __shfl_xor_sync(0xffffffffu, s0, 2);
            s1 += __shfl_xor_sync(0xffffffffu, s1, 1);
            s1 += __shfl_xor_sync(0xffffffffu, s1, 2);
            r0[nf] = sqrtf(s0);
            r1[nf] = sqrtf(s1);
        }
        if (tg == 0) {
            int row = m0 + warp_m * 64 + mf * 16 + g;
            float* p0 = out + (size_t)row * NUM_CAPS + capbase;
            float* p1 = out + (size_t)(row + 8) * NUM_CAPS + capbase;
            *reinterpret_cast<float4*>(p0)     = make_float4(r0[0], r0[1], r0[2], r0[3]);
            *reinterpret_cast<float4*>(p0 + 4) = make_float4(r0[4], r0[5], r0[6], r0[7]);
            *reinterpret_cast<float4*>(p1)     = make_float4(r1[0], r1[1], r1[2], r1[3]);
            *reinterpret_cast<float4*>(p1 + 4) = make_float4(r1[4], r1[5], r1[6], r1[7]);
        }
    }
}

// ---------------------------------------------------------------------------
extern "C" void kernel_launch(void* const* d_in, const int* in_sizes, int n_in,
                              void* d_out, int out_size) {
    (void)in_sizes; (void)n_in; (void)out_size;
    const float* x = (const float*)d_in[0];
    // d_in[1] = eye (unused; eps*I applied analytically)
    const float* w = (const float*)d_in[2];
    float* out = (float*)d_out;

    conv_x_kernel<<<(BATCH * KDIM / 4) / 256, 256>>>(
        reinterpret_cast<const float4*>(x));
    prep_w_kernel<<<NUM_CAPS, 256>>>(w);

    cudaFuncSetAttribute(caps_gemm_kernel,
                         cudaFuncAttributeMaxDynamicSharedMemorySize, SMEM_TOTAL);
    caps_gemm_kernel<<<dim3(NTOT / BN, BATCH / BM), 256, SMEM_TOTAL>>>(out);
}